// round 2
// baseline (speedup 1.0000x reference)
#include <cuda_runtime.h>
#include <cuda_bf16.h>
#include <cstdint>

#define DINL __device__ __forceinline__

// ======================= helpers =======================
DINL uint32_t smem_u32(const void* p) {
    uint32_t a;
    asm("{ .reg .u64 t; cvta.to.shared.u64 t, %1; cvt.u32.u64 %0, t; }" : "=r"(a) : "l"(p));
    return a;
}

DINL void ldsm_x4(uint32_t r[4], uint32_t addr) {
    asm volatile("ldmatrix.sync.aligned.m8n8.x4.shared.b16 {%0,%1,%2,%3}, [%4];"
        : "=r"(r[0]), "=r"(r[1]), "=r"(r[2]), "=r"(r[3]) : "r"(addr));
}
DINL void ldsm_x2(uint32_t r[2], uint32_t addr) {
    asm volatile("ldmatrix.sync.aligned.m8n8.x2.shared.b16 {%0,%1}, [%2];"
        : "=r"(r[0]), "=r"(r[1]) : "r"(addr));
}
DINL void mma_bf16(float c[4], const uint32_t a[4], const uint32_t b[2]) {
    asm volatile("mma.sync.aligned.m16n8k16.row.col.f32.bf16.bf16.f32 "
        "{%0,%1,%2,%3}, {%4,%5,%6,%7}, {%8,%9}, {%0,%1,%2,%3};"
        : "+f"(c[0]), "+f"(c[1]), "+f"(c[2]), "+f"(c[3])
        : "r"(a[0]), "r"(a[1]), "r"(a[2]), "r"(a[3]), "r"(b[0]), "r"(b[1]));
}
#define STS32(a, v) asm volatile("st.shared.b32 [%0], %1;" :: "r"(a), "r"(v) : "memory")
#define STS64(a, v) asm volatile("st.shared.b64 [%0], %1;" :: "r"(a), "l"(v) : "memory")

// ======================= packing =======================
DINL uint32_t pack2(float a, float b) {
    return ((uint32_t)__bfloat16_as_ushort(__float2bfloat16(b)) << 16)
         |  (uint32_t)__bfloat16_as_ushort(__float2bfloat16(a));
}
DINL uint64_t pack4(float a, float b, float c, float d) {
    return ((uint64_t)pack2(c, d) << 32) | (uint64_t)pack2(a, b);
}
DINL float rlo(float f) { return f - __bfloat162float(__float2bfloat16(f)); }

// ======================= SMEM layout =======================
// [0, 64K)       : per-warp A/h buffers: warp w at w*8192 (hi 4096 + lo 4096)
// [64K, 192K)    : weight images W1hi, W1lo, W2hi, W2lo (32K each), [n][k] swizzled
// [192K+4K ...]  : b1 (512B), b2 (512B)
static constexpr int OFF_W  = 65536;
static constexpr int OFF_B1 = OFF_W + 131072;   // 196608
static constexpr int OFF_B2 = OFF_B1 + 512;     // 197120
static constexpr int SMEM_TOTAL = OFF_B2 + 512; // 197632

// Swizzled element address within a [rows][128] bf16 tile (256B row):
//   addr = row*256 + ((col/8) ^ (row&7))*16 + (col%8)*2
DINL uint32_t tile_addr(int row, int col) {
    return (uint32_t)(row * 256 + (((col >> 3) ^ (row & 7)) << 4) + ((col & 7) << 1));
}

// ======================= device globals =======================
__device__ __align__(16) unsigned char g_wimg[4 * 32768];
__device__ int g_idx64;

// ======================= prologue: weight images =======================
__global__ void prep_kernel(const float* __restrict__ W1, const float* __restrict__ W2,
                            const void* __restrict__ nbr_raw) {
    int n = blockIdx.x;    // output channel (B tile row)
    int k = threadIdx.x;   // reduction index
    float w1e = W1[k * 128 + n] + W1[(k + 128) * 128 + n];  // fold concat
    float w2v = W2[k * 128 + n];
    uint32_t a = tile_addr(n, k);
    __nv_bfloat16 h1 = __float2bfloat16(w1e);
    __nv_bfloat16 l1 = __float2bfloat16(w1e - __bfloat162float(h1));
    __nv_bfloat16 h2 = __float2bfloat16(w2v);
    __nv_bfloat16 l2 = __float2bfloat16(w2v - __bfloat162float(h2));
    *(__nv_bfloat16*)(g_wimg +     0 + a) = h1;
    *(__nv_bfloat16*)(g_wimg + 32768 + a) = l1;
    *(__nv_bfloat16*)(g_wimg + 65536 + a) = h2;
    *(__nv_bfloat16*)(g_wimg + 98304 + a) = l2;

    if (blockIdx.x == 0 && threadIdx.x == 0) {
        // int64 indices (values < 50000) have zero high words; int32 data won't.
        const unsigned* w = (const unsigned*)nbr_raw;
        int is64 = 1;
        for (int i = 0; i < 64; i++)
            if (w[2 * i + 1] != 0u) { is64 = 0; break; }
        g_idx64 = is64;
    }
}

// ======================= main kernel =======================
__global__ void __launch_bounds__(256, 1)
gs_kernel(const float* __restrict__ x, const void* __restrict__ nbr_raw,
          const float* __restrict__ b1, const float* __restrict__ b2,
          float* __restrict__ out, int E) {
    extern __shared__ unsigned char sm[];
    const uint32_t sb = smem_u32(sm);
    const int tid = threadIdx.x, wid = tid >> 5, lane = tid & 31;

    // Load weight images + biases once per CTA
    {
        const uint4* s = (const uint4*)g_wimg;
        uint4* d = (uint4*)(sm + OFF_W);
#pragma unroll 4
        for (int i = tid; i < 131072 / 16; i += 256) d[i] = s[i];
    }
    if (tid < 128) {
        ((float*)(sm + OFF_B1))[tid] = b1[tid];
        ((float*)(sm + OFF_B2))[tid] = b2[tid];
    }
    __syncthreads();

    const float* b1s = (const float*)(sm + OFF_B1);
    const float* b2s = (const float*)(sm + OFF_B2);
    const uint32_t AHI = sb + (uint32_t)wid * 8192u;     // 16x128 bf16 hi
    const uint32_t ALO = AHI + 4096u;                    // lo
    const uint32_t W1H = sb + OFF_W, W1L = W1H + 32768u;
    const uint32_t W2H = W1L + 32768u, W2L = W2H + 32768u;

    // per-lane ldmatrix addressing precompute
    const int li = lane & 7, lg = lane >> 3;
    const int arow = ((lg & 1) << 3) + li;   // A-row within 16 (x4 grouping)
    const int akh  = lg >> 1;                // k half (0/1)
    const uint32_t arowoff = (uint32_t)arow * 256u;
    const int arx = arow & 7;
    const int bg = lg & 1;                   // B x2 grouping (lanes 16-31 mirror 0-15)

    const int use64 = g_idx64;
    const long long* nbr64 = (const long long*)nbr_raw;
    const int* nbr32 = (const int*)nbr_raw;

    const int ngroups = (E + 15) >> 4;
    const int gwarp = blockIdx.x * 8 + wid;
    const int nwarps = gridDim.x * 8;

    for (int grp = gwarp; grp < ngroups; grp += nwarps) {
        const int rowbase = grp << 4;

        // ---- gather 16 rows; fp32 -> bf16 hi/lo split into swizzled SMEM ----
        long long myidx = 0;
        if (lane < 16) {
            int gr = rowbase + lane;
            if (gr < E) myidx = use64 ? nbr64[gr] : (long long)nbr32[gr];
        }
        {
            // store offsets for this lane: col j = lane*4
            const uint32_t within = (uint32_t)((lane & 1) << 3);
            const int cstore = lane >> 1;
#pragma unroll 4
            for (int r = 0; r < 16; r++) {
                long long gi = __shfl_sync(0xffffffffu, myidx, r);
                const float4 v = *(const float4*)(x + gi * 128 + (lane << 2));
                uint32_t off = (uint32_t)(r * 256) + (uint32_t)((cstore ^ (r & 7)) << 4) + within;
                STS64(AHI + off, pack4(v.x, v.y, v.z, v.w));
                STS64(ALO + off, pack4(rlo(v.x), rlo(v.y), rlo(v.z), rlo(v.w)));
            }
        }
        __syncwarp();

        // ---- load A fragments (both GEMMs use this register pattern) ----
        uint32_t Ah[8][4], Al[8][4];
#pragma unroll
        for (int ks = 0; ks < 8; ks++) {
            uint32_t c = (uint32_t)((((ks << 1) + akh) ^ arx) << 4);
            ldsm_x4(Ah[ks], AHI + arowoff + c);
            ldsm_x4(Al[ks], ALO + arowoff + c);
        }
        __syncwarp();   // everyone done reading A before h overwrites it

        // ---- GEMM1: h = relu(g @ W1eff + b1), write h hi/lo back over A ----
#pragma unroll 1
        for (int nc = 0; nc < 16; nc++) {
            const int nrow = (nc << 3) + li;
            const uint32_t nbase = (uint32_t)nrow * 256u;
            const int nrx = nrow & 7;
            uint32_t Bh[8][2], Bl[8][2];
#pragma unroll
            for (int ks = 0; ks < 8; ks++) {
                uint32_t c = (uint32_t)((((ks << 1) + bg) ^ nrx) << 4);
                ldsm_x2(Bh[ks], W1H + nbase + c);
                ldsm_x2(Bl[ks], W1L + nbase + c);
            }
            float acc[4] = {0.f, 0.f, 0.f, 0.f};
#pragma unroll
            for (int ks = 0; ks < 8; ks++) mma_bf16(acc, Ah[ks], Bh[ks]);
#pragma unroll
            for (int ks = 0; ks < 8; ks++) {
                mma_bf16(acc, Ah[ks], Bl[ks]);
                mma_bf16(acc, Al[ks], Bh[ks]);
            }
            // epilogue: +b1, relu, split, store h (cols n0,n0+1; rows lane/4, +8)
            const int n0 = (nc << 3) + ((lane & 3) << 1);
            const float f0 = fmaxf(acc[0] + b1s[n0], 0.f);
            const float f1 = fmaxf(acc[1] + b1s[n0 + 1], 0.f);
            const float f2 = fmaxf(acc[2] + b1s[n0], 0.f);
            const float f3 = fmaxf(acc[3] + b1s[n0 + 1], 0.f);
            const int r0 = lane >> 2, r1 = r0 + 8;
            const uint32_t w0 = (uint32_t)((n0 & 7) << 1);
            uint32_t a0 = (uint32_t)(r0 * 256) + (uint32_t)((nc ^ (r0 & 7)) << 4) + w0;
            uint32_t a1 = (uint32_t)(r1 * 256) + (uint32_t)((nc ^ (r1 & 7)) << 4) + w0;
            STS32(AHI + a0, pack2(f0, f1));
            STS32(ALO + a0, pack2(rlo(f0), rlo(f1)));
            STS32(AHI + a1, pack2(f2, f3));
            STS32(ALO + a1, pack2(rlo(f2), rlo(f3)));
        }
        __syncwarp();

        // ---- reload A fragments from h ----
#pragma unroll
        for (int ks = 0; ks < 8; ks++) {
            uint32_t c = (uint32_t)((((ks << 1) + akh) ^ arx) << 4);
            ldsm_x4(Ah[ks], AHI + arowoff + c);
            ldsm_x4(Al[ks], ALO + arowoff + c);
        }

        // ---- GEMM2: y = h @ W2 + b2, direct global store ----
        const int mg0 = rowbase + (lane >> 2);
        const int mg1 = mg0 + 8;
        float* orow0 = out + (size_t)mg0 * 128;
        float* orow1 = out + (size_t)mg1 * 128;
#pragma unroll 1
        for (int nc = 0; nc < 16; nc++) {
            const int nrow = (nc << 3) + li;
            const uint32_t nbase = (uint32_t)nrow * 256u;
            const int nrx = nrow & 7;
            uint32_t Bh[8][2], Bl[8][2];
#pragma unroll
            for (int ks = 0; ks < 8; ks++) {
                uint32_t c = (uint32_t)((((ks << 1) + bg) ^ nrx) << 4);
                ldsm_x2(Bh[ks], W2H + nbase + c);
                ldsm_x2(Bl[ks], W2L + nbase + c);
            }
            float acc[4] = {0.f, 0.f, 0.f, 0.f};
#pragma unroll
            for (int ks = 0; ks < 8; ks++) mma_bf16(acc, Ah[ks], Bh[ks]);
#pragma unroll
            for (int ks = 0; ks < 8; ks++) {
                mma_bf16(acc, Ah[ks], Bl[ks]);
                mma_bf16(acc, Al[ks], Bh[ks]);
            }
            const int n0 = (nc << 3) + ((lane & 3) << 1);
            if (mg0 < E)
                *(float2*)(orow0 + n0) = make_float2(acc[0] + b2s[n0], acc[1] + b2s[n0 + 1]);
            if (mg1 < E)
                *(float2*)(orow1 + n0) = make_float2(acc[2] + b2s[n0], acc[3] + b2s[n0 + 1]);
        }
        __syncwarp();   // h buffer reused by next iteration's gather
    }
}

// ======================= launch =======================
extern "C" void kernel_launch(void* const* d_in, const int* in_sizes, int n_in,
                              void* d_out, int out_size) {
    const float* x  = (const float*)d_in[0];
    const void*  nb = d_in[1];
    const float* W1 = (const float*)d_in[2];
    const float* b1 = (const float*)d_in[3];
    const float* W2 = (const float*)d_in[4];
    const float* b2 = (const float*)d_in[5];
    float* out = (float*)d_out;
    const int E = in_sizes[1];

    prep_kernel<<<128, 128>>>(W1, W2, nb);

    int dev = 0;
    cudaGetDevice(&dev);
    int sms = 148;
    cudaDeviceGetAttribute(&sms, cudaDevAttrMultiProcessorCount, dev);
    const int ngroups = (E + 15) >> 4;
    int grid = sms;
    const int maxg = (ngroups + 7) / 8;
    if (grid > maxg) grid = maxg;

    cudaFuncSetAttribute(gs_kernel, cudaFuncAttributeMaxDynamicSharedMemorySize, SMEM_TOTAL);
    gs_kernel<<<grid, 256, SMEM_TOTAL>>>(x, nb, b1, b2, out, E);
}